// round 3
// baseline (speedup 1.0000x reference)
#include <cuda_runtime.h>

// MultiConvPerm: out[co,ci,:] is a 1024-length row that is zero except for a
// 57-tap stencil (wrapped across the row boundary) built from 12 dilated
// kernels mixed by gumbel-softmax coefficients.
//
// KD = [(k,d) for k in (3,5,7,9) for d in (1,3,7)], S = 57.
// Tap positions t = (S - (d*(k-1)+1))//2 + d*j are compile-time constants.

#define NW 12
#define NTAPS 72
#define S_LEN 57
#define NROWS 65536  // CO*CI = 256*256

// per-weight kernel length
__constant__ int c_k[NW] = {3,3,3, 5,5,5, 7,7,7, 9,9,9};

// flat tap tables: which weight, which tap index j, which acc position t
__constant__ unsigned char c_tap_w[NTAPS] = {
    0,0,0,
    1,1,1,
    2,2,2,
    3,3,3,3,3,
    4,4,4,4,4,
    5,5,5,5,5,
    6,6,6,6,6,6,6,
    7,7,7,7,7,7,7,
    8,8,8,8,8,8,8,
    9,9,9,9,9,9,9,9,9,
    10,10,10,10,10,10,10,10,10,
    11,11,11,11,11,11,11,11,11
};
__constant__ unsigned char c_tap_j[NTAPS] = {
    0,1,2,
    0,1,2,
    0,1,2,
    0,1,2,3,4,
    0,1,2,3,4,
    0,1,2,3,4,
    0,1,2,3,4,5,6,
    0,1,2,3,4,5,6,
    0,1,2,3,4,5,6,
    0,1,2,3,4,5,6,7,8,
    0,1,2,3,4,5,6,7,8,
    0,1,2,3,4,5,6,7,8
};
__constant__ unsigned char c_tap_t[NTAPS] = {
    27,28,29,            // k=3,d=1  p=27
    25,28,31,            // k=3,d=3  p=25
    21,28,35,            // k=3,d=7  p=21
    26,27,28,29,30,      // k=5,d=1  p=26
    22,25,28,31,34,      // k=5,d=3  p=22
    14,21,28,35,42,      // k=5,d=7  p=14
    25,26,27,28,29,30,31,        // k=7,d=1  p=25
    19,22,25,28,31,34,37,        // k=7,d=3  p=19
    7,14,21,28,35,42,49,         // k=7,d=7  p=7
    24,25,26,27,28,29,30,31,32,  // k=9,d=1  p=24
    16,19,22,25,28,31,34,37,40,  // k=9,d=3  p=16
    0,7,14,21,28,35,42,49,56     // k=9,d=7  p=0
};

struct WPtrs {
    const float* w[NW];
};

__global__ __launch_bounds__(256, 8)
void multiconv_kernel(WPtrs wp, const float* __restrict__ alpha,
                      const float* __restrict__ gumbels,
                      float* __restrict__ out, int W) {
    __shared__ float s_coef[NW];
    __shared__ float s_acc[S_LEN];

    const int tid = threadIdx.x;
    const int row = blockIdx.x;  // co*CI + ci

    if (tid < S_LEN) s_acc[tid] = 0.0f;
    if (tid == 0) {
        // coef = softmax(alpha + gumbels)  (log_softmax shift cancels)
        float v[NW];
        float m = -1e30f;
        #pragma unroll
        for (int i = 0; i < NW; i++) {
            v[i] = alpha[i] + gumbels[i];
            m = fmaxf(m, v[i]);
        }
        float s = 0.0f;
        #pragma unroll
        for (int i = 0; i < NW; i++) {
            v[i] = expf(v[i] - m);
            s += v[i];
        }
        const float inv = 1.0f / s;
        #pragma unroll
        for (int i = 0; i < NW; i++) s_coef[i] = v[i] * inv;
    }
    __syncthreads();

    if (tid < NTAPS) {
        const int wi = c_tap_w[tid];
        const float val = wp.w[wi][row * c_k[wi] + c_tap_j[tid]];
        atomicAdd(&s_acc[c_tap_t[tid]], s_coef[wi] * val);
    }
    __syncthreads();

    // out[x] = acc[28-x]    for x in [0,28]
    // out[x] = acc[W+28-x]  for x in [W-28, W-1]
    // out[x] = 0            otherwise
    float* orow = out + (size_t)row * (size_t)W;
    const int lo = 29;        // first zero index
    const int hi = W - 28;    // first wrap index

    for (int x0 = tid * 4; x0 < W; x0 += blockDim.x * 4) {
        float4 v;
        {
            int x = x0 + 0;
            v.x = (x < lo) ? s_acc[28 - x] : ((x >= hi) ? s_acc[W + 28 - x] : 0.0f);
        }
        {
            int x = x0 + 1;
            v.y = (x < lo) ? s_acc[28 - x] : ((x >= hi) ? s_acc[W + 28 - x] : 0.0f);
        }
        {
            int x = x0 + 2;
            v.z = (x < lo) ? s_acc[28 - x] : ((x >= hi) ? s_acc[W + 28 - x] : 0.0f);
        }
        {
            int x = x0 + 3;
            v.w = (x < lo) ? s_acc[28 - x] : ((x >= hi) ? s_acc[W + 28 - x] : 0.0f);
        }
        *reinterpret_cast<float4*>(orow + x0) = v;
    }
}

extern "C" void kernel_launch(void* const* d_in, const int* in_sizes, int n_in,
                              void* d_out, int out_size) {
    WPtrs wp;
    for (int i = 0; i < NW; i++) wp.w[i] = (const float*)d_in[i];
    const float* alpha = (const float*)d_in[12];
    const float* gumbels = (const float*)d_in[13];
    float* out = (float*)d_out;

    const int W = out_size / NROWS;  // spatial size (1024)

    multiconv_kernel<<<NROWS, 256>>>(wp, alpha, gumbels, out, W);
}

// round 4
// speedup vs baseline: 3.0315x; 3.0315x over previous
#include <cuda_runtime.h>

// MultiConvPerm: out[co,ci,:] is a W=1024 row, zero except a 57-tap stencil
// wrapped across the row boundary:
//   out[x] = acc[28-x]     for x in [0,28]
//   out[x] = acc[W+28-x]   for x in [W-28, W-1]
// acc is the gumbel-softmax-mixed sum of 12 dilated kernels (72 static taps).
//
// Structure: prepass kernel computes coef[12] once (softmax(alpha+gumbels),
// log_softmax shift cancels); main kernel is warp-per-row with no block-wide
// barriers, specialized for W=1024 so middle stores are pure zero streams.

#define NW 12
#define NTAPS 72
#define NROWS 65536            // CO*CI = 256*256
#define WARPS_PER_BLOCK 8
#define ROWS_PER_WARP 4

__device__ float g_coef[NW];

// per-weight kernel length
__constant__ int c_k[NW] = {3,3,3, 5,5,5, 7,7,7, 9,9,9};

// flat tap tables: which weight, which tap index j, which acc position t
__constant__ unsigned char c_tap_w[NTAPS] = {
    0,0,0, 1,1,1, 2,2,2,
    3,3,3,3,3, 4,4,4,4,4, 5,5,5,5,5,
    6,6,6,6,6,6,6, 7,7,7,7,7,7,7, 8,8,8,8,8,8,8,
    9,9,9,9,9,9,9,9,9, 10,10,10,10,10,10,10,10,10, 11,11,11,11,11,11,11,11,11
};
__constant__ unsigned char c_tap_j[NTAPS] = {
    0,1,2, 0,1,2, 0,1,2,
    0,1,2,3,4, 0,1,2,3,4, 0,1,2,3,4,
    0,1,2,3,4,5,6, 0,1,2,3,4,5,6, 0,1,2,3,4,5,6,
    0,1,2,3,4,5,6,7,8, 0,1,2,3,4,5,6,7,8, 0,1,2,3,4,5,6,7,8
};
__constant__ unsigned char c_tap_t[NTAPS] = {
    27,28,29,            // k=3,d=1  p=27
    25,28,31,            // k=3,d=3  p=25
    21,28,35,            // k=3,d=7  p=21
    26,27,28,29,30,      // k=5,d=1  p=26
    22,25,28,31,34,      // k=5,d=3  p=22
    14,21,28,35,42,      // k=5,d=7  p=14
    25,26,27,28,29,30,31,        // k=7,d=1  p=25
    19,22,25,28,31,34,37,        // k=7,d=3  p=19
    7,14,21,28,35,42,49,         // k=7,d=7  p=7
    24,25,26,27,28,29,30,31,32,  // k=9,d=1  p=24
    16,19,22,25,28,31,34,37,40,  // k=9,d=3  p=16
    0,7,14,21,28,35,42,49,56     // k=9,d=7  p=0
};

struct WPtrs {
    const float* w[NW];
};

// ---------------- prepass: coef = softmax(alpha + gumbels) -----------------
__global__ void coef_kernel(const float* __restrict__ alpha,
                            const float* __restrict__ gumbels) {
    if (threadIdx.x == 0) {
        float v[NW];
        float m = -1e30f;
        #pragma unroll
        for (int i = 0; i < NW; i++) {
            v[i] = alpha[i] + gumbels[i];
            m = fmaxf(m, v[i]);
        }
        float s = 0.0f;
        #pragma unroll
        for (int i = 0; i < NW; i++) {
            v[i] = expf(v[i] - m);
            s += v[i];
        }
        const float inv = 1.0f / s;
        #pragma unroll
        for (int i = 0; i < NW; i++) g_coef[i] = v[i] * inv;
    }
}

// ---------------- main: warp-per-row streaming stores ----------------------
template<bool FAST1024>
__global__ __launch_bounds__(WARPS_PER_BLOCK * 32, 8)
void multiconv_kernel(WPtrs wp, float* __restrict__ out, int W) {
    __shared__ float s_acc[WARPS_PER_BLOCK][64];

    const int warp = threadIdx.x >> 5;
    const int lane = threadIdx.x & 31;

    // coef broadcast: 12 L2-hit loads per thread, uniform address
    float coef[NW];
    #pragma unroll
    for (int i = 0; i < NW; i++) coef[i] = g_coef[i];

    float* acc = s_acc[warp];
    const int row0 = (blockIdx.x * WARPS_PER_BLOCK + warp) * ROWS_PER_WARP;

    #pragma unroll
    for (int r = 0; r < ROWS_PER_WARP; r++) {
        const int row = row0 + r;
        if (row >= NROWS) break;

        // zero this warp's accumulator
        acc[lane] = 0.0f;
        acc[lane + 32] = 0.0f;
        __syncwarp();

        // scatter the 72 taps (lane handles taps lane, lane+32, lane+64)
        #pragma unroll
        for (int t = lane; t < NTAPS; t += 32) {
            const int wi = c_tap_w[t];
            const float val = wp.w[wi][row * c_k[wi] + c_tap_j[t]];
            atomicAdd(&acc[c_tap_t[t]], coef[wi] * val);
        }
        __syncwarp();

        float* orow = out + (size_t)row * (size_t)W;

        if (FAST1024) {
            // iteration 0: x in [0,128): nonzero only for x <= 28 (lanes 0..7)
            {
                const int x = lane * 4;
                float4 v;
                v.x = (x + 0 < 29) ? acc[28 - (x + 0)] : 0.0f;
                v.y = (x + 1 < 29) ? acc[28 - (x + 1)] : 0.0f;
                v.z = (x + 2 < 29) ? acc[28 - (x + 2)] : 0.0f;
                v.w = (x + 3 < 29) ? acc[28 - (x + 3)] : 0.0f;
                *reinterpret_cast<float4*>(orow + x) = v;
            }
            // iterations 1..6: pure zeros
            const float4 z = make_float4(0.f, 0.f, 0.f, 0.f);
            #pragma unroll
            for (int it = 1; it < 7; it++) {
                *reinterpret_cast<float4*>(orow + it * 128 + lane * 4) = z;
            }
            // iteration 7: x in [896,1024): nonzero for x >= 996 (lanes 25..31)
            {
                const int x = 896 + lane * 4;
                float4 v;
                v.x = (x + 0 >= 996) ? acc[1052 - (x + 0)] : 0.0f;
                v.y = (x + 1 >= 996) ? acc[1052 - (x + 1)] : 0.0f;
                v.z = (x + 2 >= 996) ? acc[1052 - (x + 2)] : 0.0f;
                v.w = (x + 3 >= 996) ? acc[1052 - (x + 3)] : 0.0f;
                *reinterpret_cast<float4*>(orow + x) = v;
            }
        } else {
            const int lo = 29;
            const int hi = W - 28;
            for (int x0 = lane * 4; x0 < W; x0 += 128) {
                float4 v;
                #pragma unroll
                for (int q = 0; q < 4; q++) {
                    const int x = x0 + q;
                    float f = 0.0f;
                    if (x < lo) f = acc[28 - x];
                    else if (x >= hi) f = acc[W + 28 - x];
                    (&v.x)[q] = f;
                }
                *reinterpret_cast<float4*>(orow + x0) = v;
            }
        }
        __syncwarp();  // protect acc before next row reuses it
    }
}

extern "C" void kernel_launch(void* const* d_in, const int* in_sizes, int n_in,
                              void* d_out, int out_size) {
    WPtrs wp;
    for (int i = 0; i < NW; i++) wp.w[i] = (const float*)d_in[i];
    const float* alpha = (const float*)d_in[12];
    const float* gumbels = (const float*)d_in[13];
    float* out = (float*)d_out;

    const int W = out_size / NROWS;  // spatial size (1024)

    coef_kernel<<<1, 32>>>(alpha, gumbels);

    const int rows_per_block = WARPS_PER_BLOCK * ROWS_PER_WARP;
    const int grid = (NROWS + rows_per_block - 1) / rows_per_block;

    if (W == 1024) {
        multiconv_kernel<true><<<grid, WARPS_PER_BLOCK * 32>>>(wp, out, W);
    } else {
        multiconv_kernel<false><<<grid, WARPS_PER_BLOCK * 32>>>(wp, out, W);
    }
}

// round 6
// speedup vs baseline: 4.1068x; 1.3547x over previous
#include <cuda_runtime.h>

// MultiConvPerm: out[co,ci,:] is a W=1024 row, zero except a 57-tap stencil
// wrapped across the row boundary:
//   out[x] = acc[28-x]     for x in [0,28]
//   out[x] = acc[W+28-x]   for x in [W-28, W-1]
// acc[t] = sum over static contributors (wi,j) of coef[wi]*w[wi][row*k+j],
// where t = p_wi + d_wi*j. Inverted tap table (per t) removes all atomics.

#define NW 12
#define NROWS 65536            // CO*CI = 256*256
#define WARPS_PER_BLOCK 8
#define ROWS_PER_WARP 4

__device__ float g_coef[NW];
__device__ __align__(16) unsigned char g_tbl[NW * 64];  // tbl[wi][t] = j+1 (0 = none)

__constant__ int c_k[NW] = {3,3,3, 5,5,5, 7,7,7, 9,9,9};
__constant__ int c_d[NW] = {1,3,7, 1,3,7, 1,3,7, 1,3,7};
__constant__ int c_p[NW] = {27,25,21, 26,22,14, 25,19,7, 24,16,0};  // (57-(d*(k-1)+1))/2

struct WPtrs {
    const float* w[NW];
};

// ---------------- prepass: coef = softmax(alpha+gumbels); build tap table ---
__global__ void coef_kernel(const float* __restrict__ alpha,
                            const float* __restrict__ gumbels) {
    if (threadIdx.x == 0) {
        float v[NW];
        float m = -1e30f;
        #pragma unroll
        for (int i = 0; i < NW; i++) {
            v[i] = alpha[i] + gumbels[i];
            m = fmaxf(m, v[i]);
        }
        float s = 0.0f;
        #pragma unroll
        for (int i = 0; i < NW; i++) {
            v[i] = expf(v[i] - m);
            s += v[i];
        }
        const float inv = 1.0f / s;
        #pragma unroll
        for (int i = 0; i < NW; i++) g_coef[i] = v[i] * inv;

        // inverted tap table: tbl[wi][p + d*j] = j+1
        for (int i = 0; i < NW * 64; i++) g_tbl[i] = 0;
        #pragma unroll
        for (int wi = 0; wi < NW; wi++) {
            for (int j = 0; j < c_k[wi]; j++) {
                g_tbl[wi * 64 + c_p[wi] + c_d[wi] * j] = (unsigned char)(j + 1);
            }
        }
    }
}

// ---------------- main: warp-per-row streaming stores, no atomics ----------
template<bool FAST1024>
__global__ __launch_bounds__(WARPS_PER_BLOCK * 32, 6)
void multiconv_kernel(WPtrs wp, float* __restrict__ out, int W) {
    __shared__ float s_acc[WARPS_PER_BLOCK][ROWS_PER_WARP][64];
    __shared__ unsigned char s_tbl[NW * 64];
    __shared__ float s_coef[NW];

    const int tid = threadIdx.x;
    const int warp = tid >> 5;
    const int lane = tid & 31;

    // stage table + coefs to shared (once per block)
    if (tid < (NW * 64) / 4) {
        reinterpret_cast<unsigned int*>(s_tbl)[tid] =
            reinterpret_cast<const unsigned int*>(g_tbl)[tid];
    }
    if (tid < NW) s_coef[tid] = g_coef[tid];

    const int row0 = (blockIdx.x * WARPS_PER_BLOCK + warp) * ROWS_PER_WARP;

    // ---- phase A: pure zero stream for the middle 768 floats of each row ----
    if (FAST1024) {
        const float4 z = make_float4(0.f, 0.f, 0.f, 0.f);
        #pragma unroll
        for (int r = 0; r < ROWS_PER_WARP; r++) {
            float* orow = out + (size_t)(row0 + r) * 1024;
            #pragma unroll
            for (int it = 1; it < 7; it++) {
                *reinterpret_cast<float4*>(orow + it * 128 + lane * 4) = z;
            }
        }
    }

    __syncthreads();

    // ---- phase B: compute acc for all rows (lane owns t=lane and t=lane+32) -
    float f0[ROWS_PER_WARP], f1[ROWS_PER_WARP];
    #pragma unroll
    for (int r = 0; r < ROWS_PER_WARP; r++) { f0[r] = 0.0f; f1[r] = 0.0f; }

    const bool hasHi = (lane < 25);  // t in [32,56]

    #pragma unroll
    for (int wi = 0; wi < NW; wi++) {
        const int jv1 = s_tbl[wi * 64 + lane];
        const int jv2 = hasHi ? s_tbl[wi * 64 + lane + 32] : 0;
        const float c = s_coef[wi];
        const int kk = c_k[wi];
        const float* base = wp.w[wi] + (size_t)row0 * kk;
        #pragma unroll
        for (int r = 0; r < ROWS_PER_WARP; r++) {
            if (jv1) f0[r] += c * base[r * kk + (jv1 - 1)];
            if (jv2) f1[r] += c * base[r * kk + (jv2 - 1)];
        }
    }

    #pragma unroll
    for (int r = 0; r < ROWS_PER_WARP; r++) {
        s_acc[warp][r][lane] = f0[r];
        if (hasHi) s_acc[warp][r][lane + 32] = f1[r];
    }
    __syncwarp();

    // ---- phase C: edge stores ----
    if (FAST1024) {
        #pragma unroll
        for (int r = 0; r < ROWS_PER_WARP; r++) {
            const float* A = s_acc[warp][r];
            float* orow = out + (size_t)(row0 + r) * 1024;
            // head: x in [0,128), nonzero for x <= 28
            {
                const int x = lane * 4;
                float4 v;
                v.x = (x + 0 < 29) ? A[28 - (x + 0)] : 0.0f;
                v.y = (x + 1 < 29) ? A[28 - (x + 1)] : 0.0f;
                v.z = (x + 2 < 29) ? A[28 - (x + 2)] : 0.0f;
                v.w = (x + 3 < 29) ? A[28 - (x + 3)] : 0.0f;
                *reinterpret_cast<float4*>(orow + x) = v;
            }
            // tail: x in [896,1024), nonzero for x >= 996
            {
                const int x = 896 + lane * 4;
                float4 v;
                v.x = (x + 0 >= 996) ? A[1052 - (x + 0)] : 0.0f;
                v.y = (x + 1 >= 996) ? A[1052 - (x + 1)] : 0.0f;
                v.z = (x + 2 >= 996) ? A[1052 - (x + 2)] : 0.0f;
                v.w = (x + 3 >= 996) ? A[1052 - (x + 3)] : 0.0f;
                *reinterpret_cast<float4*>(orow + x) = v;
            }
        }
    } else {
        // generic W fallback
        const int lo = 29;
        const int hi = W - 28;
        #pragma unroll
        for (int r = 0; r < ROWS_PER_WARP; r++) {
            const float* A = s_acc[warp][r];
            float* orow = out + (size_t)(row0 + r) * (size_t)W;
            for (int x0 = lane * 4; x0 < W; x0 += 128) {
                float4 v;
                #pragma unroll
                for (int q = 0; q < 4; q++) {
                    const int x = x0 + q;
                    float f = 0.0f;
                    if (x < lo) f = A[28 - x];
                    else if (x >= hi) f = A[W + 28 - x];
                    (&v.x)[q] = f;
                }
                *reinterpret_cast<float4*>(orow + x0) = v;
            }
        }
    }
}

extern "C" void kernel_launch(void* const* d_in, const int* in_sizes, int n_in,
                              void* d_out, int out_size) {
    WPtrs wp;
    for (int i = 0; i < NW; i++) wp.w[i] = (const float*)d_in[i];
    const float* alpha = (const float*)d_in[12];
    const float* gumbels = (const float*)d_in[13];
    float* out = (float*)d_out;

    const int W = out_size / NROWS;  // spatial size (1024)

    coef_kernel<<<1, 32>>>(alpha, gumbels);

    const int rows_per_block = WARPS_PER_BLOCK * ROWS_PER_WARP;
    const int grid = (NROWS + rows_per_block - 1) / rows_per_block;

    if (W == 1024) {
        multiconv_kernel<true><<<grid, WARPS_PER_BLOCK * 32>>>(wp, out, W);
    } else {
        multiconv_kernel<false><<<grid, WARPS_PER_BLOCK * 32>>>(wp, out, W);
    }
}

// round 7
// speedup vs baseline: 4.1343x; 1.0067x over previous
#include <cuda_runtime.h>
#include <math.h>

// MultiConvPerm, fully fused single kernel.
// out[co,ci,:] (W=1024) is zero except:
//   out[x] = acc[28-x]    for x in [0,28]
//   out[x] = acc[1052-x]  for x in [996,1023]
// acc[t] = sum over static (wi,j) with t = p_wi + d_wi*j of coef[wi]*w_wi[row,j]
// coef   = softmax(alpha + gumbels)   (log_softmax shift cancels)
//
// Register-only: lane owns acc[lane] (f0) and acc[lane+32] (f1, lanes 0..24);
// epilogue permutation done via __shfl_sync. No shared memory, no barriers.

#define NW 12
#define NROWS 65536            // CO*CI = 256*256
#define WARPS_PER_BLOCK 8
#define ROWS_PER_WARP 4

struct WPtrs {
    const float* w[NW];
};

// compile-time tap geometry (KD = product((3,5,7,9),(1,3,7)), S=57)
__device__ __forceinline__ void tap_params(int wi, int& k, int& d, int& p) {
    const int ks[NW] = {3,3,3, 5,5,5, 7,7,7, 9,9,9};
    const int ds[NW] = {1,3,7, 1,3,7, 1,3,7, 1,3,7};
    const int ps[NW] = {27,25,21, 26,22,14, 25,19,7, 24,16,0};
    k = ks[wi]; d = ds[wi]; p = ps[wi];
}

__global__ __launch_bounds__(WARPS_PER_BLOCK * 32)
void multiconv_kernel(WPtrs wp, const float* __restrict__ alpha,
                      const float* __restrict__ gumbels,
                      float* __restrict__ out) {
    const int tid = threadIdx.x;
    const int warp = tid >> 5;
    const int lane = tid & 31;

    const int row0 = (blockIdx.x * WARPS_PER_BLOCK + warp) * ROWS_PER_WARP;

    // ---- phase A: fire the 24 independent zero stores immediately ----------
    {
        const float4 z = make_float4(0.f, 0.f, 0.f, 0.f);
        #pragma unroll
        for (int r = 0; r < ROWS_PER_WARP; r++) {
            float* orow = out + (size_t)(row0 + r) * 1024;
            #pragma unroll
            for (int it = 1; it < 7; it++) {
                *reinterpret_cast<float4*>(orow + it * 128 + lane * 4) = z;
            }
        }
    }

    // ---- coef = softmax(alpha + gumbels), redundant per thread -------------
    float coef[NW];
    {
        float m = -1e30f;
        #pragma unroll
        for (int i = 0; i < NW; i++) {
            coef[i] = alpha[i] + gumbels[i];
            m = fmaxf(m, coef[i]);
        }
        float s = 0.0f;
        #pragma unroll
        for (int i = 0; i < NW; i++) {
            coef[i] = expf(coef[i] - m);
            s += coef[i];
        }
        const float inv = 1.0f / s;
        #pragma unroll
        for (int i = 0; i < NW; i++) coef[i] *= inv;
    }

    // ---- phase B: per-lane accumulators over static taps -------------------
    // lane owns t0 = lane (f0) and t1 = lane+32 (f1, valid t1 <= 56)
    float f0[ROWS_PER_WARP], f1[ROWS_PER_WARP];
    #pragma unroll
    for (int r = 0; r < ROWS_PER_WARP; r++) { f0[r] = 0.0f; f1[r] = 0.0f; }

    const int t0 = lane;
    const int t1 = lane + 32;
    const bool hasHi = (lane < 25);

    #pragma unroll
    for (int wi = 0; wi < NW; wi++) {
        int k, d, p;
        tap_params(wi, k, d, p);

        const int u0 = t0 - p;
        const int u1 = t1 - p;
        const bool v0 = (u0 >= 0) && (u0 % d == 0) && (u0 / d < k);
        const bool v1 = hasHi && (u1 >= 0) && (u1 % d == 0) && (u1 / d < k);
        const int j0 = u0 / d;
        const int j1 = u1 / d;

        const float c = coef[wi];
        const float* base = wp.w[wi] + (size_t)row0 * k;
        #pragma unroll
        for (int r = 0; r < ROWS_PER_WARP; r++) {
            if (v0) f0[r] += c * base[r * k + j0];
            if (v1) f1[r] += c * base[r * k + j1];
        }
    }

    // ---- phase C: edge stores via warp shuffles ----------------------------
    #pragma unroll
    for (int r = 0; r < ROWS_PER_WARP; r++) {
        float* orow = out + (size_t)(row0 + r) * 1024;

        // head: x = 4*lane + q, out = (x<=28) ? acc[28-x] : 0
        {
            float4 v;
            #pragma unroll
            for (int q = 0; q < 4; q++) {
                const int t = 28 - (4 * lane + q);     // may be negative
                const float a = __shfl_sync(0xFFFFFFFFu, f0[r], t & 31);
                (&v.x)[q] = (t >= 0) ? a : 0.0f;
            }
            *reinterpret_cast<float4*>(orow + lane * 4) = v;
        }
        // tail: x = 896 + 4*lane + q, t = 1052-x = 156-4*lane-q,
        //       out = (29<=t<=56) ? acc[t] : 0
        {
            float4 v;
            #pragma unroll
            for (int q = 0; q < 4; q++) {
                const int t = 156 - 4 * lane - q;
                const float alo = __shfl_sync(0xFFFFFFFFu, f0[r], t & 31);
                const float ahi = __shfl_sync(0xFFFFFFFFu, f1[r], (t - 32) & 31);
                float a = (t >= 32) ? ahi : alo;
                (&v.x)[q] = (t >= 29 && t <= 56) ? a : 0.0f;
            }
            *reinterpret_cast<float4*>(orow + 896 + lane * 4) = v;
        }
    }
}

// ---------------- generic-W fallback (shared-memory variant) ----------------
__global__ __launch_bounds__(WARPS_PER_BLOCK * 32)
void multiconv_generic(WPtrs wp, const float* __restrict__ alpha,
                       const float* __restrict__ gumbels,
                       float* __restrict__ out, int W) {
    __shared__ float s_acc[WARPS_PER_BLOCK][ROWS_PER_WARP][64];

    const int tid = threadIdx.x;
    const int warp = tid >> 5;
    const int lane = tid & 31;
    const int row0 = (blockIdx.x * WARPS_PER_BLOCK + warp) * ROWS_PER_WARP;

    float coef[NW];
    {
        float m = -1e30f;
        #pragma unroll
        for (int i = 0; i < NW; i++) {
            coef[i] = alpha[i] + gumbels[i];
            m = fmaxf(m, coef[i]);
        }
        float s = 0.0f;
        #pragma unroll
        for (int i = 0; i < NW; i++) { coef[i] = expf(coef[i] - m); s += coef[i]; }
        const float inv = 1.0f / s;
        #pragma unroll
        for (int i = 0; i < NW; i++) coef[i] *= inv;
    }

    float f0[ROWS_PER_WARP], f1[ROWS_PER_WARP];
    #pragma unroll
    for (int r = 0; r < ROWS_PER_WARP; r++) { f0[r] = 0.0f; f1[r] = 0.0f; }

    const bool hasHi = (lane < 25);
    #pragma unroll
    for (int wi = 0; wi < NW; wi++) {
        int k, d, p;
        tap_params(wi, k, d, p);
        const int u0 = lane - p, u1 = lane + 32 - p;
        const bool v0 = (u0 >= 0) && (u0 % d == 0) && (u0 / d < k);
        const bool v1 = hasHi && (u1 >= 0) && (u1 % d == 0) && (u1 / d < k);
        const int j0 = u0 / d, j1 = u1 / d;
        const float c = coef[wi];
        const float* base = wp.w[wi] + (size_t)row0 * k;
        #pragma unroll
        for (int r = 0; r < ROWS_PER_WARP; r++) {
            if (v0) f0[r] += c * base[r * k + j0];
            if (v1) f1[r] += c * base[r * k + j1];
        }
    }
    #pragma unroll
    for (int r = 0; r < ROWS_PER_WARP; r++) {
        s_acc[warp][r][lane] = f0[r];
        if (hasHi) s_acc[warp][r][lane + 32] = f1[r];
    }
    __syncwarp();

    const int lo = 29, hi = W - 28;
    #pragma unroll
    for (int r = 0; r < ROWS_PER_WARP; r++) {
        const float* A = s_acc[warp][r];
        float* orow = out + (size_t)(row0 + r) * (size_t)W;
        for (int x0 = lane * 4; x0 < W; x0 += 128) {
            float4 v;
            #pragma unroll
            for (int q = 0; q < 4; q++) {
                const int x = x0 + q;
                float f = 0.0f;
                if (x < lo) f = A[28 - x];
                else if (x >= hi) f = A[W + 28 - x];
                (&v.x)[q] = f;
            }
            *reinterpret_cast<float4*>(orow + x0) = v;
        }
    }
}

extern "C" void kernel_launch(void* const* d_in, const int* in_sizes, int n_in,
                              void* d_out, int out_size) {
    WPtrs wp;
    for (int i = 0; i < NW; i++) wp.w[i] = (const float*)d_in[i];
    const float* alpha = (const float*)d_in[12];
    const float* gumbels = (const float*)d_in[13];
    float* out = (float*)d_out;

    const int W = out_size / NROWS;  // spatial size (1024)
    const int rows_per_block = WARPS_PER_BLOCK * ROWS_PER_WARP;
    const int grid = (NROWS + rows_per_block - 1) / rows_per_block;

    if (W == 1024) {
        multiconv_kernel<<<grid, WARPS_PER_BLOCK * 32>>>(wp, alpha, gumbels, out);
    } else {
        multiconv_generic<<<grid, WARPS_PER_BLOCK * 32>>>(wp, alpha, gumbels, out, W);
    }
}

// round 8
// speedup vs baseline: 4.1366x; 1.0006x over previous
#include <cuda_runtime.h>
#include <math.h>

// MultiConvPerm, fused single kernel.
// out[co,ci,:] (W=1024) is zero except:
//   out[x] = acc[28-x]    for x in [0,28]
//   out[x] = acc[1052-x]  for x in [996,1023]
// acc[t] = sum over static (wi,j) with t = p_wi + d_wi*j of coef[wi]*w_wi[row,j]
// coef   = softmax(alpha + gumbels)   (log_softmax shift cancels)
//
// Phase A: stream the 768 middle zeros of each row first (pure STG.128).
// Softmax computed per-thread with __expf (hides under store drain).
// Phase B: per-lane tap accumulation, predicates are compile-time arithmetic.
// Phase C: edge stores through a per-warp shared accumulator (no block syncs).

#define NW 12
#define NROWS 65536            // CO*CI = 256*256
#define WARPS_PER_BLOCK 8
#define ROWS_PER_WARP 4

struct WPtrs {
    const float* w[NW];
};

// compile-time tap geometry (KD = product((3,5,7,9),(1,3,7)), S=57)
__device__ __forceinline__ void tap_params(int wi, int& k, int& d, int& p) {
    const int ks[NW] = {3,3,3, 5,5,5, 7,7,7, 9,9,9};
    const int ds[NW] = {1,3,7, 1,3,7, 1,3,7, 1,3,7};
    const int ps[NW] = {27,25,21, 26,22,14, 25,19,7, 24,16,0};
    k = ks[wi]; d = ds[wi]; p = ps[wi];
}

template<bool FAST1024>
__global__ __launch_bounds__(WARPS_PER_BLOCK * 32)
void multiconv_kernel(WPtrs wp, const float* __restrict__ alpha,
                      const float* __restrict__ gumbels,
                      float* __restrict__ out, int W) {
    __shared__ float s_acc[WARPS_PER_BLOCK][ROWS_PER_WARP][64];

    const int tid = threadIdx.x;
    const int warp = tid >> 5;
    const int lane = tid & 31;

    const int row0 = (blockIdx.x * WARPS_PER_BLOCK + warp) * ROWS_PER_WARP;

    // ---- phase A: fire the independent zero stores immediately -------------
    if (FAST1024) {
        const float4 z = make_float4(0.f, 0.f, 0.f, 0.f);
        #pragma unroll
        for (int r = 0; r < ROWS_PER_WARP; r++) {
            float* orow = out + (size_t)(row0 + r) * 1024;
            #pragma unroll
            for (int it = 1; it < 7; it++) {
                *reinterpret_cast<float4*>(orow + it * 128 + lane * 4) = z;
            }
        }
    }

    // ---- coef = softmax(alpha + gumbels), fast-math, hides under stores ----
    float coef[NW];
    {
        float m = -1e30f;
        #pragma unroll
        for (int i = 0; i < NW; i++) {
            coef[i] = alpha[i] + gumbels[i];
            m = fmaxf(m, coef[i]);
        }
        float s = 0.0f;
        #pragma unroll
        for (int i = 0; i < NW; i++) {
            coef[i] = __expf(coef[i] - m);   // MUFU ex2 path
            s += coef[i];
        }
        const float inv = __fdividef(1.0f, s);
        #pragma unroll
        for (int i = 0; i < NW; i++) coef[i] *= inv;
    }

    // ---- phase B: per-lane accumulators over static taps -------------------
    // lane owns t0 = lane and t1 = lane+32 (valid while t1 <= 56)
    float f0[ROWS_PER_WARP], f1[ROWS_PER_WARP];
    #pragma unroll
    for (int r = 0; r < ROWS_PER_WARP; r++) { f0[r] = 0.0f; f1[r] = 0.0f; }

    const bool hasHi = (lane < 25);

    #pragma unroll
    for (int wi = 0; wi < NW; wi++) {
        int k, d, p;
        tap_params(wi, k, d, p);

        const int u0 = lane - p;
        const int u1 = lane + 32 - p;
        const bool v0 = (u0 >= 0) && (u0 % d == 0) && (u0 / d < k);
        const bool v1 = hasHi && (u1 >= 0) && (u1 % d == 0) && (u1 / d < k);
        const int j0 = u0 / d;
        const int j1 = u1 / d;

        const float c = coef[wi];
        const float* base = wp.w[wi] + (size_t)row0 * k;
        #pragma unroll
        for (int r = 0; r < ROWS_PER_WARP; r++) {
            if (v0) f0[r] += c * base[r * k + j0];
            if (v1) f1[r] += c * base[r * k + j1];
        }
    }

    #pragma unroll
    for (int r = 0; r < ROWS_PER_WARP; r++) {
        s_acc[warp][r][lane] = f0[r];
        if (hasHi) s_acc[warp][r][lane + 32] = f1[r];
    }
    __syncwarp();

    // ---- phase C: edge stores ----------------------------------------------
    if (FAST1024) {
        #pragma unroll
        for (int r = 0; r < ROWS_PER_WARP; r++) {
            const float* A = s_acc[warp][r];
            float* orow = out + (size_t)(row0 + r) * 1024;
            // head: x in [0,128), nonzero for x <= 28
            {
                const int x = lane * 4;
                float4 v;
                v.x = (x + 0 < 29) ? A[28 - (x + 0)] : 0.0f;
                v.y = (x + 1 < 29) ? A[28 - (x + 1)] : 0.0f;
                v.z = (x + 2 < 29) ? A[28 - (x + 2)] : 0.0f;
                v.w = (x + 3 < 29) ? A[28 - (x + 3)] : 0.0f;
                *reinterpret_cast<float4*>(orow + x) = v;
            }
            // tail: x in [896,1024), nonzero for x >= 996
            {
                const int x = 896 + lane * 4;
                float4 v;
                v.x = (x + 0 >= 996) ? A[1052 - (x + 0)] : 0.0f;
                v.y = (x + 1 >= 996) ? A[1052 - (x + 1)] : 0.0f;
                v.z = (x + 2 >= 996) ? A[1052 - (x + 2)] : 0.0f;
                v.w = (x + 3 >= 996) ? A[1052 - (x + 3)] : 0.0f;
                *reinterpret_cast<float4*>(orow + x) = v;
            }
        }
    } else {
        const int lo = 29, hi = W - 28;
        #pragma unroll
        for (int r = 0; r < ROWS_PER_WARP; r++) {
            const float* A = s_acc[warp][r];
            float* orow = out + (size_t)(row0 + r) * (size_t)W;
            for (int x0 = lane * 4; x0 < W; x0 += 128) {
                float4 v;
                #pragma unroll
                for (int q = 0; q < 4; q++) {
                    const int x = x0 + q;
                    float f = 0.0f;
                    if (x < lo) f = A[28 - x];
                    else if (x >= hi) f = A[W + 28 - x];
                    (&v.x)[q] = f;
                }
                *reinterpret_cast<float4*>(orow + x0) = v;
            }
        }
    }
}

extern "C" void kernel_launch(void* const* d_in, const int* in_sizes, int n_in,
                              void* d_out, int out_size) {
    WPtrs wp;
    for (int i = 0; i < NW; i++) wp.w[i] = (const float*)d_in[i];
    const float* alpha = (const float*)d_in[12];
    const float* gumbels = (const float*)d_in[13];
    float* out = (float*)d_out;

    const int W = out_size / NROWS;  // spatial size (1024)
    const int rows_per_block = WARPS_PER_BLOCK * ROWS_PER_WARP;
    const int grid = (NROWS + rows_per_block - 1) / rows_per_block;

    if (W == 1024) {
        multiconv_kernel<true><<<grid, WARPS_PER_BLOCK * 32>>>(wp, alpha, gumbels, out, W);
    } else {
        multiconv_kernel<false><<<grid, WARPS_PER_BLOCK * 32>>>(wp, alpha, gumbels, out, W);
    }
}

// round 9
// speedup vs baseline: 4.2479x; 1.0269x over previous
#include <cuda_runtime.h>
#include <math.h>

// MultiConvPerm, fused single kernel, hybrid store path:
//   - middle 768 floats of each 1024-row are zeros -> cp.async.bulk (3KB/row)
//     from a shared 3KB zero buffer (same source for every row)
//   - head/tail 128-float edge segments -> STG.128 from per-warp smem acc
//
// out[co,ci,:] (W=1024) is zero except:
//   out[x] = acc[28-x]    for x in [0,28]
//   out[x] = acc[1052-x]  for x in [996,1023]
// acc[t] = sum over static (wi,j) with t = p_wi + d_wi*j of coef[wi]*w_wi[row,j]
// coef   = softmax(alpha + gumbels)   (log_softmax shift cancels)

#define NW 12
#define NROWS 65536            // CO*CI = 256*256
#define WARPS_PER_BLOCK 8
#define ROWS_PER_WARP 4
#define ZERO_FLOATS 768        // middle floats per row, 3072 bytes

struct WPtrs {
    const float* w[NW];
};

// compile-time tap geometry (KD = product((3,5,7,9),(1,3,7)), S=57)
__device__ __forceinline__ void tap_params(int wi, int& k, int& d, int& p) {
    const int ks[NW] = {3,3,3, 5,5,5, 7,7,7, 9,9,9};
    const int ds[NW] = {1,3,7, 1,3,7, 1,3,7, 1,3,7};
    const int ps[NW] = {27,25,21, 26,22,14, 25,19,7, 24,16,0};
    k = ks[wi]; d = ds[wi]; p = ps[wi];
}

__device__ __forceinline__ unsigned int smem_u32(const void* p) {
    return (unsigned int)__cvta_generic_to_shared(p);
}

template<bool FAST1024>
__global__ __launch_bounds__(WARPS_PER_BLOCK * 32)
void multiconv_kernel(WPtrs wp, const float* __restrict__ alpha,
                      const float* __restrict__ gumbels,
                      float* __restrict__ out, int W) {
    __shared__ __align__(16) float s_zero[ZERO_FLOATS];
    __shared__ float s_acc[WARPS_PER_BLOCK][ROWS_PER_WARP][64];

    const int tid = threadIdx.x;
    const int warp = tid >> 5;
    const int lane = tid & 31;

    const int row0 = (blockIdx.x * WARPS_PER_BLOCK + warp) * ROWS_PER_WARP;

    // ---- init shared zero buffer (once per block) --------------------------
    if (FAST1024) {
        if (tid < ZERO_FLOATS / 4) {
            reinterpret_cast<float4*>(s_zero)[tid] = make_float4(0.f, 0.f, 0.f, 0.f);
        }
        // make generic-proxy smem writes visible to the async (bulk-copy) proxy
        asm volatile("fence.proxy.async.shared::cta;" ::: "memory");
        __syncthreads();

        // ---- phase A: one 3KB bulk zero-store per row, deep async queue ----
        if (lane == 0) {
            const unsigned int src = smem_u32(s_zero);
            #pragma unroll
            for (int r = 0; r < ROWS_PER_WARP; r++) {
                float* dst = out + (size_t)(row0 + r) * 1024 + 128;
                asm volatile(
                    "cp.async.bulk.global.shared::cta.bulk_group [%0], [%1], %2;"
                    :: "l"(dst), "r"(src), "r"(ZERO_FLOATS * 4) : "memory");
            }
            asm volatile("cp.async.bulk.commit_group;" ::: "memory");
        }
    }

    // ---- coef = softmax(alpha + gumbels), fast-math ------------------------
    float coef[NW];
    {
        float m = -1e30f;
        #pragma unroll
        for (int i = 0; i < NW; i++) {
            coef[i] = alpha[i] + gumbels[i];
            m = fmaxf(m, coef[i]);
        }
        float s = 0.0f;
        #pragma unroll
        for (int i = 0; i < NW; i++) {
            coef[i] = __expf(coef[i] - m);
            s += coef[i];
        }
        const float inv = __fdividef(1.0f, s);
        #pragma unroll
        for (int i = 0; i < NW; i++) coef[i] *= inv;
    }

    // ---- phase B: per-lane accumulators over static taps -------------------
    // lane owns t0 = lane and t1 = lane+32 (valid while t1 <= 56)
    float f0[ROWS_PER_WARP], f1[ROWS_PER_WARP];
    #pragma unroll
    for (int r = 0; r < ROWS_PER_WARP; r++) { f0[r] = 0.0f; f1[r] = 0.0f; }

    const bool hasHi = (lane < 25);

    #pragma unroll
    for (int wi = 0; wi < NW; wi++) {
        int k, d, p;
        tap_params(wi, k, d, p);

        const int u0 = lane - p;
        const int u1 = lane + 32 - p;
        const bool v0 = (u0 >= 0) && (u0 % d == 0) && (u0 / d < k);
        const bool v1 = hasHi && (u1 >= 0) && (u1 % d == 0) && (u1 / d < k);
        const int j0 = u0 / d;
        const int j1 = u1 / d;

        const float c = coef[wi];
        const float* base = wp.w[wi] + (size_t)row0 * k;
        #pragma unroll
        for (int r = 0; r < ROWS_PER_WARP; r++) {
            if (v0) f0[r] += c * base[r * k + j0];
            if (v1) f1[r] += c * base[r * k + j1];
        }
    }

    #pragma unroll
    for (int r = 0; r < ROWS_PER_WARP; r++) {
        s_acc[warp][r][lane] = f0[r];
        if (hasHi) s_acc[warp][r][lane + 32] = f1[r];
    }
    __syncwarp();

    // ---- phase C: edge stores (STG.128 from smem acc) ----------------------
    if (FAST1024) {
        #pragma unroll
        for (int r = 0; r < ROWS_PER_WARP; r++) {
            const float* A = s_acc[warp][r];
            float* orow = out + (size_t)(row0 + r) * 1024;
            // head: x in [0,128), nonzero for x <= 28
            {
                const int x = lane * 4;
                float4 v;
                v.x = (x + 0 < 29) ? A[28 - (x + 0)] : 0.0f;
                v.y = (x + 1 < 29) ? A[28 - (x + 1)] : 0.0f;
                v.z = (x + 2 < 29) ? A[28 - (x + 2)] : 0.0f;
                v.w = (x + 3 < 29) ? A[28 - (x + 3)] : 0.0f;
                *reinterpret_cast<float4*>(orow + x) = v;
            }
            // tail: x in [896,1024), nonzero for x >= 996
            {
                const int x = 896 + lane * 4;
                float4 v;
                v.x = (x + 0 >= 996) ? A[1052 - (x + 0)] : 0.0f;
                v.y = (x + 1 >= 996) ? A[1052 - (x + 1)] : 0.0f;
                v.z = (x + 2 >= 996) ? A[1052 - (x + 2)] : 0.0f;
                v.w = (x + 3 >= 996) ? A[1052 - (x + 3)] : 0.0f;
                *reinterpret_cast<float4*>(orow + x) = v;
            }
        }
        // drain this warp's bulk-store group before block exit
        if (lane == 0) {
            asm volatile("cp.async.bulk.wait_group 0;" ::: "memory");
        }
    } else {
        const int lo = 29, hi = W - 28;
        #pragma unroll
        for (int r = 0; r < ROWS_PER_WARP; r++) {
            const float* A = s_acc[warp][r];
            float* orow = out + (size_t)(row0 + r) * (size_t)W;
            for (int x0 = lane * 4; x0 < W; x0 += 128) {
                float4 v;
                #pragma unroll
                for (int q = 0; q < 4; q++) {
                    const int x = x0 + q;
                    float f = 0.0f;
                    if (x < lo) f = A[28 - x];
                    else if (x >= hi) f = A[W + 28 - x];
                    (&v.x)[q] = f;
                }
                *reinterpret_cast<float4*>(orow + x0) = v;
            }
        }
    }
}

extern "C" void kernel_launch(void* const* d_in, const int* in_sizes, int n_in,
                              void* d_out, int out_size) {
    WPtrs wp;
    for (int i = 0; i < NW; i++) wp.w[i] = (const float*)d_in[i];
    const float* alpha = (const float*)d_in[12];
    const float* gumbels = (const float*)d_in[13];
    float* out = (float*)d_out;

    const int W = out_size / NROWS;  // spatial size (1024)
    const int rows_per_block = WARPS_PER_BLOCK * ROWS_PER_WARP;
    const int grid = (NROWS + rows_per_block - 1) / rows_per_block;

    if (W == 1024) {
        multiconv_kernel<true><<<grid, WARPS_PER_BLOCK * 32>>>(wp, alpha, gumbels, out, W);
    } else {
        multiconv_kernel<false><<<grid, WARPS_PER_BLOCK * 32>>>(wp, alpha, gumbels, out, W);
    }
}